// round 1
// baseline (speedup 1.0000x reference)
#include <cuda_runtime.h>
#include <math.h>

// Problem constants
#define NB 16384
#define ND 1024
#define NE 8
#define NH 512
#define NT 256
#define NTASK 3

// ---------------------------------------------------------------------------
// Scratch (device globals; no runtime allocation allowed)
// ---------------------------------------------------------------------------
__device__ float g_h1[(size_t)NE * NB * NH];              // [E,B,H] 256 MB
__device__ float g_eo[(size_t)NE * NB * NH];              // [E,B,H] 256 MB
__device__ float g_gates[(size_t)NTASK * NB * NE];        // [T,B,E]
__device__ float g_tin[(size_t)NTASK * NB * NH];          // [T,B,H] 100 MB
__device__ float g_th[(size_t)NTASK * NB * NT];           // [T,B,T] 50 MB

// ---------------------------------------------------------------------------
// Generic batched GEMM: C[z] = act(A[z] * B[z] + bias[z])
// A: [M,K] row-major, B: [K,N] row-major, C: [M,N] row-major.
// Tile: 128x128, BK=8, 256 threads, 8x8 micro-tile per thread.
// All dims assumed divisible (M%128==0, N%128==0, K%8==0) — true here.
// ---------------------------------------------------------------------------
__global__ __launch_bounds__(256)
void gemm_bias_relu(const float* __restrict__ Ab, const float* __restrict__ Bb,
                    const float* __restrict__ biasb, float* __restrict__ Cb,
                    int M, int N, int K,
                    long long sA, long long sB, long long sBias, long long sC)
{
    const int z = blockIdx.z;
    const float* A    = Ab    + (size_t)z * sA;
    const float* Bw   = Bb    + (size_t)z * sB;
    const float* bias = biasb + (size_t)z * sBias;
    float*       C    = Cb    + (size_t)z * sC;

    __shared__ float As[8][128];   // transposed A tile: As[k][m]
    __shared__ float Bs[8][128];   // Bs[k][n]

    const int tid = threadIdx.x;
    const int tx  = tid & 15;      // 0..15 -> n micro
    const int ty  = tid >> 4;      // 0..15 -> m micro
    const int m0  = blockIdx.y * 128;
    const int n0  = blockIdx.x * 128;

    float acc[8][8];
#pragma unroll
    for (int i = 0; i < 8; i++)
#pragma unroll
        for (int j = 0; j < 8; j++) acc[i][j] = 0.f;

    // A tile load mapping: 128 rows x 8 cols = 1024 floats = 256 thr * 1 float4
    const int arow = tid >> 1;          // 0..127
    const int acol = (tid & 1) * 4;     // 0 or 4
    // B tile load mapping: 8 rows x 128 cols
    const int brow = tid >> 5;          // 0..7
    const int bcol = (tid & 31) * 4;    // 0..124

    const float* Aptr = A  + (size_t)(m0 + arow) * K + acol;
    const float* Bptr = Bw + (size_t)brow * N + n0 + bcol;

    for (int k0 = 0; k0 < K; k0 += 8) {
        float4 av = *(const float4*)(Aptr + k0);
        float4 bv = *(const float4*)(Bptr + (size_t)k0 * N);
        As[acol + 0][arow] = av.x;
        As[acol + 1][arow] = av.y;
        As[acol + 2][arow] = av.z;
        As[acol + 3][arow] = av.w;
        *(float4*)&Bs[brow][bcol] = bv;
        __syncthreads();

#pragma unroll
        for (int k = 0; k < 8; k++) {
            float a[8], b[8];
            *(float4*)&a[0] = *(const float4*)&As[k][ty * 8];
            *(float4*)&a[4] = *(const float4*)&As[k][ty * 8 + 4];
            *(float4*)&b[0] = *(const float4*)&Bs[k][tx * 8];
            *(float4*)&b[4] = *(const float4*)&Bs[k][tx * 8 + 4];
#pragma unroll
            for (int i = 0; i < 8; i++)
#pragma unroll
                for (int j = 0; j < 8; j++)
                    acc[i][j] = fmaf(a[i], b[j], acc[i][j]);
        }
        __syncthreads();
    }

    // Epilogue: bias + relu, vectorized stores
#pragma unroll
    for (int i = 0; i < 8; i++) {
        const int m = m0 + ty * 8 + i;
#pragma unroll
        for (int j = 0; j < 8; j += 4) {
            const int n = n0 + tx * 8 + j;
            float4 bv = *(const float4*)(bias + n);
            float4 v;
            v.x = fmaxf(acc[i][j + 0] + bv.x, 0.f);
            v.y = fmaxf(acc[i][j + 1] + bv.y, 0.f);
            v.z = fmaxf(acc[i][j + 2] + bv.z, 0.f);
            v.w = fmaxf(acc[i][j + 3] + bv.w, 0.f);
            *(float4*)(C + (size_t)m * N + n) = v;
        }
    }
}

// ---------------------------------------------------------------------------
// Gates: logits[t,b,e] = x[b,:] . Wg[t,:,e] + bg[t,e]; softmax over e.
// One warp per row b; all 24 (t,e) accumulators live per-lane, warp-reduced.
// ---------------------------------------------------------------------------
__global__ __launch_bounds__(256)
void gates_kernel(const float* __restrict__ x, const float* __restrict__ Wg,
                  const float* __restrict__ bg, float* __restrict__ gates)
{
    const int warp = (blockIdx.x * blockDim.x + threadIdx.x) >> 5;
    const int lane = threadIdx.x & 31;
    if (warp >= NB) return;
    const int b = warp;

    float acc[NTASK][NE];
#pragma unroll
    for (int t = 0; t < NTASK; t++)
#pragma unroll
        for (int e = 0; e < NE; e++) acc[t][e] = 0.f;

    const float* xrow = x + (size_t)b * ND;
    for (int d = lane; d < ND; d += 32) {
        const float xv = xrow[d];
#pragma unroll
        for (int t = 0; t < NTASK; t++) {
            const float* w = Wg + ((size_t)t * ND + d) * NE;
            float4 w0 = *(const float4*)w;
            float4 w1 = *(const float4*)(w + 4);
            acc[t][0] = fmaf(xv, w0.x, acc[t][0]);
            acc[t][1] = fmaf(xv, w0.y, acc[t][1]);
            acc[t][2] = fmaf(xv, w0.z, acc[t][2]);
            acc[t][3] = fmaf(xv, w0.w, acc[t][3]);
            acc[t][4] = fmaf(xv, w1.x, acc[t][4]);
            acc[t][5] = fmaf(xv, w1.y, acc[t][5]);
            acc[t][6] = fmaf(xv, w1.z, acc[t][6]);
            acc[t][7] = fmaf(xv, w1.w, acc[t][7]);
        }
    }
#pragma unroll
    for (int off = 16; off > 0; off >>= 1) {
#pragma unroll
        for (int t = 0; t < NTASK; t++)
#pragma unroll
            for (int e = 0; e < NE; e++)
                acc[t][e] += __shfl_xor_sync(0xffffffffu, acc[t][e], off);
    }
    if (lane < NTASK) {
        const int t = lane;
        float v[NE];
        float mx = -1e30f;
#pragma unroll
        for (int e = 0; e < NE; e++) {
            v[e] = acc[t][e] + bg[t * NE + e];
            mx = fmaxf(mx, v[e]);
        }
        float s = 0.f;
#pragma unroll
        for (int e = 0; e < NE; e++) { v[e] = expf(v[e] - mx); s += v[e]; }
        const float inv = 1.f / s;
        float* gout = gates + ((size_t)t * NB + b) * NE;
#pragma unroll
        for (int e = 0; e < NE; e++) gout[e] = v[e] * inv;
    }
}

// ---------------------------------------------------------------------------
// Combine: tin[t,b,h] = sum_e gates[t,b,e] * eo[e,b,h]; all 3 tasks per thread
// so expert_out (256 MB) is read exactly once. Thread handles 4 h's (float4).
// ---------------------------------------------------------------------------
__global__ __launch_bounds__(256)
void combine_kernel(const float* __restrict__ eo, const float* __restrict__ gates,
                    float* __restrict__ tin)
{
    const int idx = blockIdx.x * blockDim.x + threadIdx.x;  // over B * H/4
    const int h4 = idx & (NH / 4 - 1);                      // 0..127
    const int b  = idx >> 7;
    if (b >= NB) return;

    float g[NTASK][NE];
#pragma unroll
    for (int t = 0; t < NTASK; t++) {
        const float* gp = gates + ((size_t)t * NB + b) * NE;
#pragma unroll
        for (int e = 0; e < NE; e++) g[t][e] = gp[e];
    }

    float4 o[NTASK];
#pragma unroll
    for (int t = 0; t < NTASK; t++) o[t] = make_float4(0.f, 0.f, 0.f, 0.f);

#pragma unroll
    for (int e = 0; e < NE; e++) {
        float4 v = *(const float4*)(eo + ((size_t)e * NB + b) * NH + h4 * 4);
#pragma unroll
        for (int t = 0; t < NTASK; t++) {
            o[t].x = fmaf(g[t][e], v.x, o[t].x);
            o[t].y = fmaf(g[t][e], v.y, o[t].y);
            o[t].z = fmaf(g[t][e], v.z, o[t].z);
            o[t].w = fmaf(g[t][e], v.w, o[t].w);
        }
    }
#pragma unroll
    for (int t = 0; t < NTASK; t++)
        *(float4*)(tin + ((size_t)t * NB + b) * NH + h4 * 4) = o[t];
}

// ---------------------------------------------------------------------------
// Tower head: pred[t,b] = sigmoid(th[t,b,:] . Wt2[t,:,0] + bt2[t]).
// One warp per (t,b).
// ---------------------------------------------------------------------------
__global__ __launch_bounds__(256)
void tower2_kernel(const float* __restrict__ th, const float* __restrict__ Wt2,
                   const float* __restrict__ bt2, float* __restrict__ out)
{
    const int warp = (blockIdx.x * blockDim.x + threadIdx.x) >> 5;
    const int lane = threadIdx.x & 31;
    if (warp >= NTASK * NB) return;
    const int t = warp / NB;

    const float* row = th + (size_t)warp * NT;
    const float* w   = Wt2 + (size_t)t * NT;
    float acc = 0.f;
#pragma unroll
    for (int d = lane; d < NT; d += 32) acc = fmaf(row[d], w[d], acc);
#pragma unroll
    for (int off = 16; off > 0; off >>= 1)
        acc += __shfl_xor_sync(0xffffffffu, acc, off);
    if (lane == 0) {
        const float zv = acc + bt2[t];
        out[warp] = 1.f / (1.f + expf(-zv));
    }
}

// ---------------------------------------------------------------------------
// Launch
// ---------------------------------------------------------------------------
extern "C" void kernel_launch(void* const* d_in, const int* in_sizes, int n_in,
                              void* d_out, int out_size)
{
    const float* x   = (const float*)d_in[0];
    const float* We1 = (const float*)d_in[1];
    const float* be1 = (const float*)d_in[2];
    const float* We2 = (const float*)d_in[3];
    const float* be2 = (const float*)d_in[4];
    const float* Wg  = (const float*)d_in[5];
    const float* bg  = (const float*)d_in[6];
    const float* Wt1 = (const float*)d_in[7];
    const float* bt1 = (const float*)d_in[8];
    const float* Wt2 = (const float*)d_in[9];
    const float* bt2 = (const float*)d_in[10];
    float* out = (float*)d_out;

    float *h1, *eo, *gates, *tin, *th;
    cudaGetSymbolAddress((void**)&h1,    g_h1);
    cudaGetSymbolAddress((void**)&eo,    g_eo);
    cudaGetSymbolAddress((void**)&gates, g_gates);
    cudaGetSymbolAddress((void**)&tin,   g_tin);
    cudaGetSymbolAddress((void**)&th,    g_th);

    // Expert layer 1: per e: h1_e[B,H] = relu(x[B,D] @ We1[e][D,H] + be1[e])
    gemm_bias_relu<<<dim3(NH / 128, NB / 128, NE), 256>>>(
        x, We1, be1, h1, NB, NH, ND,
        0LL, (long long)ND * NH, (long long)NH, (long long)NB * NH);

    // Expert layer 2: per e: eo_e[B,H] = relu(h1_e[B,H] @ We2[e][H,H] + be2[e])
    gemm_bias_relu<<<dim3(NH / 128, NB / 128, NE), 256>>>(
        h1, We2, be2, eo, NB, NH, NH,
        (long long)NB * NH, (long long)NH * NH, (long long)NH, (long long)NB * NH);

    // Gates (softmax over experts, per task)
    gates_kernel<<<NB / 8, 256>>>(x, Wg, bg, gates);

    // Gated combine -> task inputs [T,B,H]
    combine_kernel<<<(NB * (NH / 4)) / 256, 256>>>(eo, gates, tin);

    // Tower layer 1: per t: th_t[B,T] = relu(tin_t[B,H] @ Wt1[t][H,T] + bt1[t])
    gemm_bias_relu<<<dim3(NT / 128, NB / 128, NTASK), 256>>>(
        tin, Wt1, bt1, th, NB, NT, NH,
        (long long)NB * NH, (long long)NH * NT, (long long)NT, (long long)NB * NT);

    // Tower head + sigmoid
    tower2_kernel<<<(NTASK * NB * 32) / 256, 256>>>(th, Wt2, bt2, out);
}

// round 3
// speedup vs baseline: 3.2510x; 3.2510x over previous
#include <cuda_runtime.h>
#include <math.h>
#include <stdint.h>

// Problem constants
#define NB 16384
#define ND 1024
#define NE 8
#define NH 512
#define NT 256
#define NTASK 3

// GEMM tiling (mma.sync tf32 path)
#define TM 128
#define TN 128
#define BK 32
#define LDP 36                     // smem row pitch in floats (128B rows + 16B pad)
#define STAGE_BYTES (128 * LDP * 4)  // 18432 B per operand per stage
#define SMEM_BYTES (4 * STAGE_BYTES + 512 + 256)  // A x2, B x2, bias, pad

// ---------------------------------------------------------------------------
// Scratch (device globals; no runtime allocation allowed)
// ---------------------------------------------------------------------------
__device__ float g_h1[(size_t)NE * NB * NH];          // [E,B,H]
__device__ float g_eo[(size_t)NE * NB * NH];          // [E,B,H]
__device__ float g_gates[(size_t)NTASK * NB * NE];    // [T,B,E]
__device__ float g_tin[(size_t)NTASK * NB * NH];      // [T,B,H]
__device__ float g_th[(size_t)NTASK * NB * NT];       // [T,B,T]
__device__ float g_We1T[(size_t)NE * NH * ND];        // [E,H,D] transposed+tf32
__device__ float g_We2T[(size_t)NE * NH * NH];        // [E,H,H]
__device__ float g_Wt1T[(size_t)NTASK * NT * NH];     // [T,NT,H]

// ---------------------------------------------------------------------------
// Helpers (all sm_80-class PTX; nothing gated on the 'a' feature set)
// ---------------------------------------------------------------------------
__device__ __forceinline__ uint32_t smem_u32(const void* p) {
    uint32_t a;
    asm("{ .reg .u64 t; cvta.to.shared.u64 t, %1; cvt.u32.u64 %0, t; }" : "=r"(a) : "l"(p));
    return a;
}

__device__ __forceinline__ uint32_t f32_to_tf32(float x) {
    uint32_t u;
    asm("cvt.rna.tf32.f32 %0, %1;" : "=r"(u) : "f"(x));
    return u;
}

__device__ __forceinline__ float to_tf32f(float x) {
    return __uint_as_float(f32_to_tf32(x));
}

#define CP_ASYNC16(dst, src) \
    asm volatile("cp.async.cg.shared.global [%0], [%1], 16;" :: "r"(dst), "l"(src))
#define CP_COMMIT() asm volatile("cp.async.commit_group;" ::: "memory")
#define CP_WAIT1()  asm volatile("cp.async.wait_group 1;" ::: "memory")
#define CP_WAIT0()  asm volatile("cp.async.wait_group 0;" ::: "memory")

__device__ __forceinline__ void mma_tf32(float (&d)[4], const uint32_t (&a)[4],
                                         const uint32_t (&b)[2]) {
    asm volatile(
        "mma.sync.aligned.m16n8k8.row.col.f32.tf32.tf32.f32 "
        "{%0,%1,%2,%3}, {%4,%5,%6,%7}, {%8,%9}, {%0,%1,%2,%3};"
        : "+f"(d[0]), "+f"(d[1]), "+f"(d[2]), "+f"(d[3])
        : "r"(a[0]), "r"(a[1]), "r"(a[2]), "r"(a[3]), "r"(b[0]), "r"(b[1]));
}

// ---------------------------------------------------------------------------
// Weight transpose + tf32 round: in [z][K][N] -> out [z][N][K]
// ---------------------------------------------------------------------------
__global__ __launch_bounds__(256)
void transpose_round_kernel(const float* __restrict__ in, float* __restrict__ out,
                            int K, int N)
{
    __shared__ float t[32][33];
    const int z = blockIdx.z;
    in  += (size_t)z * K * N;
    out += (size_t)z * K * N;
    const int k0 = blockIdx.y * 32, n0 = blockIdx.x * 32;
    const int tx = threadIdx.x & 31, ty = threadIdx.x >> 5;  // 32 x 8
#pragma unroll
    for (int i = 0; i < 32; i += 8)
        t[ty + i][tx] = in[(size_t)(k0 + ty + i) * N + n0 + tx];
    __syncthreads();
#pragma unroll
    for (int i = 0; i < 32; i += 8)
        out[(size_t)(n0 + ty + i) * K + k0 + tx] = to_tf32f(t[tx][ty + i]);
}

// ---------------------------------------------------------------------------
// tf32 tensor-core batched GEMM: C[z] = relu(A[z] @ Bt[z]^T + bias[z])
//   A : [M, K] row-major (fp32; rounded to tf32 at fragment load)
//   Bt: [N, K] row-major (already tf32-rounded by transpose kernel)
// CTA tile 128x128, BK=32, double-buffered cp.async, 8 warps (4M x 2N),
// warp tile 32x64 via m16n8k8 atoms.
// ---------------------------------------------------------------------------
__global__ __launch_bounds__(256)
void gemm_tf32_kernel(const float* __restrict__ Ab, const float* __restrict__ Bb,
                      const float* __restrict__ biasb, float* __restrict__ Cb,
                      int K, int ldc,
                      long long sA, long long sB, long long sBias, long long sC)
{
    extern __shared__ char dynsmem[];
    const uint32_t smb = smem_u32(dynsmem);

    const int z = blockIdx.z;
    const float* A    = Ab + (size_t)z * sA + (size_t)(blockIdx.y * TM) * K;
    const float* Bt   = Bb + (size_t)z * sB + (size_t)(blockIdx.x * TN) * K;
    const float* bias = biasb + (size_t)z * sBias + blockIdx.x * TN;
    float*       C    = Cb + (size_t)z * sC + (size_t)(blockIdx.y * TM) * ldc + blockIdx.x * TN;

    const int tid  = threadIdx.x;
    const int wid  = tid >> 5;
    const int lane = tid & 31;
    const int gid  = lane >> 2;   // group id (0..7)
    const int tig  = lane & 3;    // thread-in-group (0..3)
    const int warpM = wid >> 1;   // 0..3  -> 32-row slab
    const int warpN = wid & 1;    // 0..1  -> 64-col slab

    float* bias_s = (float*)(dynsmem + 4 * STAGE_BYTES);
    if (tid < TN) bias_s[tid] = bias[tid];

    // stage loader: A tile 128x32 + B tile 128x32, float4 cp.async
    auto load_stage = [&](int buf, int k0) {
        const float* Ag = A + k0;
        const float* Bg = Bt + k0;
#pragma unroll
        for (int i = 0; i < 4; i++) {
            const int idx = tid + i * 256;        // 0..1023
            const int row = idx >> 3;             // 0..127
            const int c4  = idx & 7;              // 0..7 (float4 within 32 k)
            const uint32_t off = (uint32_t)(row * (LDP * 4) + c4 * 16);
            CP_ASYNC16(smb + buf * STAGE_BYTES + off, Ag + (size_t)row * K + c4 * 4);
            CP_ASYNC16(smb + 2 * STAGE_BYTES + buf * STAGE_BYTES + off,
                       Bg + (size_t)row * K + c4 * 4);
        }
        CP_COMMIT();
    };

    float acc[2][8][4];
#pragma unroll
    for (int mt = 0; mt < 2; mt++)
#pragma unroll
        for (int nt = 0; nt < 8; nt++)
#pragma unroll
            for (int r = 0; r < 4; r++) acc[mt][nt][r] = 0.f;

    const int ns = K / BK;
    load_stage(0, 0);
    load_stage(1, BK);

    for (int s = 0; s < ns; s++) {
        if (s + 1 < ns) CP_WAIT1(); else CP_WAIT0();
        __syncthreads();

        const int buf = s & 1;
        const float (*As)[LDP] = (const float (*)[LDP])(dynsmem + buf * STAGE_BYTES);
        const float (*Bs)[LDP] = (const float (*)[LDP])(dynsmem + 2 * STAGE_BYTES + buf * STAGE_BYTES);

#pragma unroll
        for (int kk = 0; kk < 4; kk++) {
            const int kb = kk * 8;
            uint32_t af[2][4];
#pragma unroll
            for (int mt = 0; mt < 2; mt++) {
                const int r = warpM * 32 + mt * 16 + gid;
                af[mt][0] = f32_to_tf32(As[r][kb + tig]);
                af[mt][1] = f32_to_tf32(As[r + 8][kb + tig]);
                af[mt][2] = f32_to_tf32(As[r][kb + tig + 4]);
                af[mt][3] = f32_to_tf32(As[r + 8][kb + tig + 4]);
            }
            uint32_t bf[8][2];
#pragma unroll
            for (int nt = 0; nt < 8; nt++) {
                const int c = warpN * 64 + nt * 8 + gid;
                bf[nt][0] = __float_as_uint(Bs[c][kb + tig]);       // pre-rounded
                bf[nt][1] = __float_as_uint(Bs[c][kb + tig + 4]);
            }
#pragma unroll
            for (int mt = 0; mt < 2; mt++)
#pragma unroll
                for (int nt = 0; nt < 8; nt++)
                    mma_tf32(acc[mt][nt], af[mt], bf[nt]);
        }
        __syncthreads();
        if (s + 2 < ns) load_stage(buf, (s + 2) * BK);
    }

    // Epilogue: bias + relu, float2 stores
#pragma unroll
    for (int mt = 0; mt < 2; mt++) {
        const int r0 = warpM * 32 + mt * 16 + gid;
#pragma unroll
        for (int nt = 0; nt < 8; nt++) {
            const int c = warpN * 64 + nt * 8 + tig * 2;
            const float2 bv = *(const float2*)(bias_s + c);
            float2 o;
            o.x = fmaxf(acc[mt][nt][0] + bv.x, 0.f);
            o.y = fmaxf(acc[mt][nt][1] + bv.y, 0.f);
            *(float2*)(C + (size_t)r0 * ldc + c) = o;
            o.x = fmaxf(acc[mt][nt][2] + bv.x, 0.f);
            o.y = fmaxf(acc[mt][nt][3] + bv.y, 0.f);
            *(float2*)(C + (size_t)(r0 + 8) * ldc + c) = o;
        }
    }
}

// ---------------------------------------------------------------------------
// Gates: logits[t,b,e] = x[b,:] . Wg[t,:,e] + bg[t,e]; softmax over e.
// ---------------------------------------------------------------------------
__global__ __launch_bounds__(256)
void gates_kernel(const float* __restrict__ x, const float* __restrict__ Wg,
                  const float* __restrict__ bg, float* __restrict__ gates)
{
    const int warp = (blockIdx.x * blockDim.x + threadIdx.x) >> 5;
    const int lane = threadIdx.x & 31;
    if (warp >= NB) return;
    const int b = warp;

    float acc[NTASK][NE];
#pragma unroll
    for (int t = 0; t < NTASK; t++)
#pragma unroll
        for (int e = 0; e < NE; e++) acc[t][e] = 0.f;

    const float* xrow = x + (size_t)b * ND;
    for (int d = lane; d < ND; d += 32) {
        const float xv = xrow[d];
#pragma unroll
        for (int t = 0; t < NTASK; t++) {
            const float* w = Wg + ((size_t)t * ND + d) * NE;
            float4 w0 = *(const float4*)w;
            float4 w1 = *(const float4*)(w + 4);
            acc[t][0] = fmaf(xv, w0.x, acc[t][0]);
            acc[t][1] = fmaf(xv, w0.y, acc[t][1]);
            acc[t][2] = fmaf(xv, w0.z, acc[t][2]);
            acc[t][3] = fmaf(xv, w0.w, acc[t][3]);
            acc[t][4] = fmaf(xv, w1.x, acc[t][4]);
            acc[t][5] = fmaf(xv, w1.y, acc[t][5]);
            acc[t][6] = fmaf(xv, w1.z, acc[t][6]);
            acc[t][7] = fmaf(xv, w1.w, acc[t][7]);
        }
    }
#pragma unroll
    for (int off = 16; off > 0; off >>= 1) {
#pragma unroll
        for (int t = 0; t < NTASK; t++)
#pragma unroll
            for (int e = 0; e < NE; e++)
                acc[t][e] += __shfl_xor_sync(0xffffffffu, acc[t][e], off);
    }
    if (lane < NTASK) {
        const int t = lane;
        float v[NE];
        float mx = -1e30f;
#pragma unroll
        for (int e = 0; e < NE; e++) {
            v[e] = acc[t][e] + bg[t * NE + e];
            mx = fmaxf(mx, v[e]);
        }
        float s = 0.f;
#pragma unroll
        for (int e = 0; e < NE; e++) { v[e] = expf(v[e] - mx); s += v[e]; }
        const float inv = 1.f / s;
        float* gout = gates + ((size_t)t * NB + b) * NE;
#pragma unroll
        for (int e = 0; e < NE; e++) gout[e] = v[e] * inv;
    }
}

// ---------------------------------------------------------------------------
// Combine: tin[t,b,h] = sum_e gates[t,b,e] * eo[e,b,h]
// ---------------------------------------------------------------------------
__global__ __launch_bounds__(256)
void combine_kernel(const float* __restrict__ eo, const float* __restrict__ gates,
                    float* __restrict__ tin)
{
    const int idx = blockIdx.x * blockDim.x + threadIdx.x;
    const int h4 = idx & (NH / 4 - 1);
    const int b  = idx >> 7;
    if (b >= NB) return;

    float g[NTASK][NE];
#pragma unroll
    for (int t = 0; t < NTASK; t++) {
        const float* gp = gates + ((size_t)t * NB + b) * NE;
#pragma unroll
        for (int e = 0; e < NE; e++) g[t][e] = gp[e];
    }

    float4 o[NTASK];
#pragma unroll
    for (int t = 0; t < NTASK; t++) o[t] = make_float4(0.f, 0.f, 0.f, 0.f);

#pragma unroll
    for (int e = 0; e < NE; e++) {
        float4 v = *(const float4*)(eo + ((size_t)e * NB + b) * NH + h4 * 4);
#pragma unroll
        for (int t = 0; t < NTASK; t++) {
            o[t].x = fmaf(g[t][e], v.x, o[t].x);
            o[t].y = fmaf(g[t][e], v.y, o[t].y);
            o[t].z = fmaf(g[t][e], v.z, o[t].z);
            o[t].w = fmaf(g[t][e], v.w, o[t].w);
        }
    }
#pragma unroll
    for (int t = 0; t < NTASK; t++)
        *(float4*)(tin + ((size_t)t * NB + b) * NH + h4 * 4) = o[t];
}

// ---------------------------------------------------------------------------
// Tower head: pred[t,b] = sigmoid(th[t,b,:] . Wt2[t,:,0] + bt2[t])
// ---------------------------------------------------------------------------
__global__ __launch_bounds__(256)
void tower2_kernel(const float* __restrict__ th, const float* __restrict__ Wt2,
                   const float* __restrict__ bt2, float* __restrict__ out)
{
    const int warp = (blockIdx.x * blockDim.x + threadIdx.x) >> 5;
    const int lane = threadIdx.x & 31;
    if (warp >= NTASK * NB) return;
    const int t = warp / NB;

    const float* row = th + (size_t)warp * NT;
    const float* w   = Wt2 + (size_t)t * NT;
    float acc = 0.f;
#pragma unroll
    for (int d = lane; d < NT; d += 32) acc = fmaf(row[d], w[d], acc);
#pragma unroll
    for (int off = 16; off > 0; off >>= 1)
        acc += __shfl_xor_sync(0xffffffffu, acc, off);
    if (lane == 0) {
        const float zv = acc + bt2[t];
        out[warp] = 1.f / (1.f + expf(-zv));
    }
}

// ---------------------------------------------------------------------------
// Launch
// ---------------------------------------------------------------------------
extern "C" void kernel_launch(void* const* d_in, const int* in_sizes, int n_in,
                              void* d_out, int out_size)
{
    const float* x   = (const float*)d_in[0];
    const float* We1 = (const float*)d_in[1];
    const float* be1 = (const float*)d_in[2];
    const float* We2 = (const float*)d_in[3];
    const float* be2 = (const float*)d_in[4];
    const float* Wg  = (const float*)d_in[5];
    const float* bg  = (const float*)d_in[6];
    const float* Wt1 = (const float*)d_in[7];
    const float* bt1 = (const float*)d_in[8];
    const float* Wt2 = (const float*)d_in[9];
    const float* bt2 = (const float*)d_in[10];
    float* out = (float*)d_out;

    float *h1, *eo, *gates, *tin, *th, *We1T, *We2T, *Wt1T;
    cudaGetSymbolAddress((void**)&h1,    g_h1);
    cudaGetSymbolAddress((void**)&eo,    g_eo);
    cudaGetSymbolAddress((void**)&gates, g_gates);
    cudaGetSymbolAddress((void**)&tin,   g_tin);
    cudaGetSymbolAddress((void**)&th,    g_th);
    cudaGetSymbolAddress((void**)&We1T,  g_We1T);
    cudaGetSymbolAddress((void**)&We2T,  g_We2T);
    cudaGetSymbolAddress((void**)&Wt1T,  g_Wt1T);

    cudaFuncSetAttribute(gemm_tf32_kernel,
                         cudaFuncAttributeMaxDynamicSharedMemorySize, SMEM_BYTES);

    // Pre-transpose + tf32-round weights
    transpose_round_kernel<<<dim3(NH / 32, ND / 32, NE), 256>>>(We1, We1T, ND, NH);
    transpose_round_kernel<<<dim3(NH / 32, NH / 32, NE), 256>>>(We2, We2T, NH, NH);
    transpose_round_kernel<<<dim3(NT / 32, NH / 32, NTASK), 256>>>(Wt1, Wt1T, NH, NT);

    // Gates (independent of expert path)
    gates_kernel<<<NB / 8, 256>>>(x, Wg, bg, gates);

    // Expert layer 1: h1[e] = relu(x @ We1[e] + be1[e])   [B,D]x[D,H]
    gemm_tf32_kernel<<<dim3(NH / TN, NB / TM, NE), 256, SMEM_BYTES>>>(
        x, We1T, be1, h1, ND, NH,
        0LL, (long long)NH * ND, (long long)NH, (long long)NB * NH);

    // Expert layer 2: eo[e] = relu(h1[e] @ We2[e] + be2[e])   [B,H]x[H,H]
    gemm_tf32_kernel<<<dim3(NH / TN, NB / TM, NE), 256, SMEM_BYTES>>>(
        h1, We2T, be2, eo, NH, NH,
        (long long)NB * NH, (long long)NH * NH, (long long)NH, (long long)NB * NH);

    // Gated combine
    combine_kernel<<<(NB * (NH / 4)) / 256, 256>>>(eo, gates, tin);

    // Tower layer 1: th[t] = relu(tin[t] @ Wt1[t] + bt1[t])   [B,H]x[H,T]
    gemm_tf32_kernel<<<dim3(NT / TN, NB / TM, NTASK), 256, SMEM_BYTES>>>(
        tin, Wt1T, bt1, th, NH, NT,
        (long long)NB * NH, (long long)NT * NH, (long long)NT, (long long)NB * NT);

    // Tower head + sigmoid
    tower2_kernel<<<(NTASK * NB * 32) / 256, 256>>>(th, Wt2, bt2, out);
}

// round 4
// speedup vs baseline: 5.0517x; 1.5539x over previous
#include <cuda_runtime.h>
#include <cuda_bf16.h>
#include <math.h>
#include <stdint.h>

// Problem constants
#define NB 16384
#define ND 1024
#define NE 8
#define NH 512
#define NT 256
#define NTASK 3

// GEMM tiling (bf16 mma.sync m16n8k16)
#define TM 128
#define TN 128
#define BK 64
#define NSTAGE 3
#define STAGE_BYTES 16384             // 128 rows x 128 B (64 bf16)
#define OFF_B (NSTAGE * STAGE_BYTES)  // 49152
#define SMEM_BYTES (2 * NSTAGE * STAGE_BYTES + 512)

// ---------------------------------------------------------------------------
// Scratch (device globals; no runtime allocation allowed)
// ---------------------------------------------------------------------------
__device__ __nv_bfloat16 g_xb[(size_t)NB * ND];            // x in bf16
__device__ __nv_bfloat16 g_h1b[(size_t)NE * NB * NH];      // [E,B,H] bf16
__device__ __nv_bfloat16 g_eob[(size_t)NE * NB * NH];      // [E,B,H] bf16
__device__ __nv_bfloat16 g_tinb[(size_t)NTASK * NB * NH];  // [T,B,H] bf16
__device__ float g_th[(size_t)NTASK * NB * NT];            // [T,B,T] fp32
__device__ float g_gates[(size_t)NTASK * NB * NE];         // [T,B,E]
__device__ float g_WgT[(size_t)NTASK * NE * ND];           // [T,E,D]
__device__ __nv_bfloat16 g_We1T[(size_t)NE * NH * ND];     // [E,H,D] bf16 NK
__device__ __nv_bfloat16 g_We2T[(size_t)NE * NH * NH];     // [E,H,H]
__device__ __nv_bfloat16 g_Wt1T[(size_t)NTASK * NT * NH];  // [T,NT,H]

// ---------------------------------------------------------------------------
// Helpers (sm_80-class PTX only)
// ---------------------------------------------------------------------------
__device__ __forceinline__ uint32_t smem_u32(const void* p) {
    uint32_t a;
    asm("{ .reg .u64 t; cvta.to.shared.u64 t, %1; cvt.u32.u64 %0, t; }" : "=r"(a) : "l"(p));
    return a;
}

#define CP_ASYNC16(dst, src) \
    asm volatile("cp.async.cg.shared.global [%0], [%1], 16;" :: "r"(dst), "l"(src))
#define CP_COMMIT() asm volatile("cp.async.commit_group;" ::: "memory")
#define CP_WAIT1()  asm volatile("cp.async.wait_group 1;" ::: "memory")
#define CP_WAIT0()  asm volatile("cp.async.wait_group 0;" ::: "memory")

__device__ __forceinline__ void ldmatrix_x4(uint32_t& r0, uint32_t& r1,
                                            uint32_t& r2, uint32_t& r3, uint32_t addr) {
    asm volatile("ldmatrix.sync.aligned.m8n8.x4.shared.b16 {%0,%1,%2,%3}, [%4];"
                 : "=r"(r0), "=r"(r1), "=r"(r2), "=r"(r3) : "r"(addr));
}

__device__ __forceinline__ void mma_bf16(float (&d)[4], const uint32_t (&a)[4],
                                         const uint32_t (&b)[2]) {
    asm volatile(
        "mma.sync.aligned.m16n8k16.row.col.f32.bf16.bf16.f32 "
        "{%0,%1,%2,%3}, {%4,%5,%6,%7}, {%8,%9}, {%0,%1,%2,%3};"
        : "+f"(d[0]), "+f"(d[1]), "+f"(d[2]), "+f"(d[3])
        : "r"(a[0]), "r"(a[1]), "r"(a[2]), "r"(a[3]), "r"(b[0]), "r"(b[1]));
}

__device__ __forceinline__ uint32_t sw128(uint32_t off) {
    return off ^ ((off >> 3) & 0x70);
}

// ---------------------------------------------------------------------------
// fp32 -> bf16 convert (x)
// ---------------------------------------------------------------------------
__global__ __launch_bounds__(256)
void f2b_kernel(const float* __restrict__ in, __nv_bfloat16* __restrict__ out, int n4)
{
    const int i = blockIdx.x * 256 + threadIdx.x;
    if (i >= n4) return;
    float4 v = ((const float4*)in)[i];
    __nv_bfloat162* o = (__nv_bfloat162*)out + i * 2;
    o[0] = __floats2bfloat162_rn(v.x, v.y);
    o[1] = __floats2bfloat162_rn(v.z, v.w);
}

// ---------------------------------------------------------------------------
// Weight transpose + bf16 convert: in fp32 [z][K][N] -> out bf16 [z][N][K]
// ---------------------------------------------------------------------------
__global__ __launch_bounds__(256)
void transpose_bf16_kernel(const float* __restrict__ in, __nv_bfloat16* __restrict__ out,
                           int K, int N)
{
    __shared__ float t[32][33];
    const int z = blockIdx.z;
    in  += (size_t)z * K * N;
    out += (size_t)z * K * N;
    const int k0 = blockIdx.y * 32, n0 = blockIdx.x * 32;
    const int tx = threadIdx.x & 31, ty = threadIdx.x >> 5;  // 32 x 8
#pragma unroll
    for (int i = 0; i < 32; i += 8)
        t[ty + i][tx] = in[(size_t)(k0 + ty + i) * N + n0 + tx];
    __syncthreads();
#pragma unroll
    for (int i = 0; i < 32; i += 8)
        out[(size_t)(n0 + ty + i) * K + k0 + tx] = __float2bfloat16_rn(t[tx][ty + i]);
}

// ---------------------------------------------------------------------------
// Wg transpose: [T,D,E] -> [T,E,D] fp32 (small)
// ---------------------------------------------------------------------------
__global__ __launch_bounds__(256)
void wg_transpose_kernel(const float* __restrict__ Wg, float* __restrict__ WgT)
{
    const int i = blockIdx.x * 256 + threadIdx.x;
    if (i >= NTASK * ND * NE) return;
    const int t = i / (ND * NE);
    const int r = i - t * ND * NE;
    const int d = r >> 3, e = r & 7;
    WgT[((size_t)t * NE + e) * ND + d] = Wg[i];
}

// ---------------------------------------------------------------------------
// bf16 tensor-core batched GEMM: C[z] = relu(A[z] @ Bt[z]^T + bias[z])
//   A : bf16 [M, K] row-major; Bt: bf16 [N, K] row-major
// CTA tile 128x128, BK=64, 3-stage cp.async, 8 warps (4M x 2N),
// m16n8k16 atoms via ldmatrix.x4. Output OutT (float or bf16), relu.
// ---------------------------------------------------------------------------
template <typename OutT>
__global__ __launch_bounds__(256)
void gemm_bf16_kernel(const __nv_bfloat16* __restrict__ Ab,
                      const __nv_bfloat16* __restrict__ Bb,
                      const float* __restrict__ biasb, OutT* __restrict__ Cb,
                      int K, int ldc,
                      long long sA, long long sB, long long sBias, long long sC)
{
    extern __shared__ char dynsmem[];
    const uint32_t smb = smem_u32(dynsmem);

    const int z = blockIdx.z;
    const __nv_bfloat16* A  = Ab + (size_t)z * sA + (size_t)(blockIdx.y * TM) * K;
    const __nv_bfloat16* Bt = Bb + (size_t)z * sB + (size_t)(blockIdx.x * TN) * K;
    const float* bias = biasb + (size_t)z * sBias + blockIdx.x * TN;
    OutT* C = Cb + (size_t)z * sC + (size_t)(blockIdx.y * TM) * ldc + blockIdx.x * TN;

    const int tid   = threadIdx.x;
    const int wid   = tid >> 5;
    const int lane  = tid & 31;
    const int gid   = lane >> 2;
    const int tig   = lane & 3;
    const int warpM = wid >> 1;   // 0..3
    const int warpN = wid & 1;    // 0..1

    float* bias_s = (float*)(dynsmem + 2 * NSTAGE * STAGE_BYTES);
    if (tid < TN) bias_s[tid] = bias[tid];

    // stage loader: 128 rows x 64 bf16 (128B) per operand
    auto load_stage = [&](int buf, int k0) {
        const __nv_bfloat16* Ag = A + k0;
        const __nv_bfloat16* Bg = Bt + k0;
#pragma unroll
        for (int i = 0; i < 4; i++) {
            const int idx = tid + i * 256;      // 0..1023
            const int row = idx >> 3;           // 0..127
            const int c8  = idx & 7;            // 16B chunk within row
            const uint32_t off = sw128((uint32_t)(row * 128 + c8 * 16));
            CP_ASYNC16(smb + buf * STAGE_BYTES + off, Ag + (size_t)row * K + c8 * 8);
            CP_ASYNC16(smb + OFF_B + buf * STAGE_BYTES + off, Bg + (size_t)row * K + c8 * 8);
        }
        CP_COMMIT();
    };

    float acc[2][8][4];
#pragma unroll
    for (int mt = 0; mt < 2; mt++)
#pragma unroll
        for (int nt = 0; nt < 8; nt++)
#pragma unroll
            for (int r = 0; r < 4; r++) acc[mt][nt][r] = 0.f;

    // ldmatrix lane address components
    const int a_row  = warpM * 32 + (lane & 15);       // + mt*16
    const int a_koff = (lane >> 4) * 16;               // + kk*32
    const int b_row  = warpN * 64 + (lane & 7) + ((lane >> 4) << 3);  // + pair*16
    const int b_koff = ((lane >> 3) & 1) * 16;         // + kk*32

    const int ns = K / BK;
    load_stage(0, 0);
    load_stage(1, BK);

    for (int s = 0; s < ns; s++) {
        if (s + 1 < ns) CP_WAIT1(); else CP_WAIT0();
        __syncthreads();

        const int buf = s % NSTAGE;
        const uint32_t sa = smb + buf * STAGE_BYTES;
        const uint32_t sb = smb + OFF_B + buf * STAGE_BYTES;

#pragma unroll
        for (int kk = 0; kk < 4; kk++) {
            uint32_t af[2][4];
#pragma unroll
            for (int mt = 0; mt < 2; mt++) {
                const uint32_t off = (uint32_t)((a_row + mt * 16) * 128 + kk * 32 + a_koff);
                ldmatrix_x4(af[mt][0], af[mt][1], af[mt][2], af[mt][3], sa + sw128(off));
            }
            uint32_t bf[8][2];
#pragma unroll
            for (int pr = 0; pr < 4; pr++) {
                const uint32_t off = (uint32_t)((b_row + pr * 16) * 128 + kk * 32 + b_koff);
                ldmatrix_x4(bf[pr * 2][0], bf[pr * 2][1], bf[pr * 2 + 1][0], bf[pr * 2 + 1][1],
                            sb + sw128(off));
            }
#pragma unroll
            for (int mt = 0; mt < 2; mt++)
#pragma unroll
                for (int nt = 0; nt < 8; nt++)
                    mma_bf16(acc[mt][nt], af[mt], bf[nt]);
        }
        __syncthreads();
        if (s + 2 < ns) load_stage((s + 2) % NSTAGE, (s + 2) * BK);
    }

    // Epilogue: bias + relu
#pragma unroll
    for (int mt = 0; mt < 2; mt++) {
        const int r0 = warpM * 32 + mt * 16 + gid;
#pragma unroll
        for (int nt = 0; nt < 8; nt++) {
            const int c = warpN * 64 + nt * 8 + tig * 2;
            const float2 bv = *(const float2*)(bias_s + c);
            float v0 = fmaxf(acc[mt][nt][0] + bv.x, 0.f);
            float v1 = fmaxf(acc[mt][nt][1] + bv.y, 0.f);
            float v2 = fmaxf(acc[mt][nt][2] + bv.x, 0.f);
            float v3 = fmaxf(acc[mt][nt][3] + bv.y, 0.f);
            if (sizeof(OutT) == 2) {
                *(__nv_bfloat162*)((__nv_bfloat16*)C + (size_t)r0 * ldc + c) =
                    __floats2bfloat162_rn(v0, v1);
                *(__nv_bfloat162*)((__nv_bfloat16*)C + (size_t)(r0 + 8) * ldc + c) =
                    __floats2bfloat162_rn(v2, v3);
            } else {
                *(float2*)((float*)C + (size_t)r0 * ldc + c) = make_float2(v0, v1);
                *(float2*)((float*)C + (size_t)(r0 + 8) * ldc + c) = make_float2(v2, v3);
            }
        }
    }
}

// ---------------------------------------------------------------------------
// Gates: smem-cached WgT [T,E,D]; block = 8 warps x 4 rows = 32 b rows.
// ---------------------------------------------------------------------------
__global__ __launch_bounds__(256)
void gates_kernel(const float* __restrict__ x, const float* __restrict__ WgT,
                  const float* __restrict__ bg, float* __restrict__ gates)
{
    extern __shared__ float wg_s[];   // [24][1024]
    const int tid = threadIdx.x;
    for (int i = tid; i < NTASK * NE * ND / 4; i += 256)
        ((float4*)wg_s)[i] = ((const float4*)WgT)[i];
    __syncthreads();

    const int wid = tid >> 5, lane = tid & 31;
#pragma unroll 1
    for (int rb = 0; rb < 4; rb++) {
        const int b = blockIdx.x * 32 + wid * 4 + rb;
        const float4* xr = (const float4*)(x + (size_t)b * ND);
        float acc[24];
#pragma unroll
        for (int te = 0; te < 24; te++) acc[te] = 0.f;
#pragma unroll
        for (int i = 0; i < 8; i++) {
            const int d4 = lane + 32 * i;
            const float4 xv = xr[d4];
#pragma unroll
            for (int te = 0; te < 24; te++) {
                const float4 wv = ((const float4*)(wg_s + te * ND))[d4];
                acc[te] += xv.x * wv.x + xv.y * wv.y + xv.z * wv.z + xv.w * wv.w;
            }
        }
#pragma unroll
        for (int off = 16; off > 0; off >>= 1)
#pragma unroll
            for (int te = 0; te < 24; te++)
                acc[te] += __shfl_xor_sync(0xffffffffu, acc[te], off);
        if (lane < NTASK) {
            const int t = lane;
            float v[NE];
            float mx = -1e30f;
#pragma unroll
            for (int e = 0; e < NE; e++) {
                v[e] = acc[t * NE + e] + bg[t * NE + e];
                mx = fmaxf(mx, v[e]);
            }
            float s = 0.f;
#pragma unroll
            for (int e = 0; e < NE; e++) { v[e] = expf(v[e] - mx); s += v[e]; }
            const float inv = 1.f / s;
            float* gout = gates + ((size_t)t * NB + b) * NE;
#pragma unroll
            for (int e = 0; e < NE; e++) gout[e] = v[e] * inv;
        }
    }
}

// ---------------------------------------------------------------------------
// Combine: tin[t,b,h] = sum_e gates[t,b,e] * eo[e,b,h]  (bf16 in/out)
// Thread handles 8 h (16B).
// ---------------------------------------------------------------------------
__global__ __launch_bounds__(256)
void combine_kernel(const __nv_bfloat16* __restrict__ eo, const float* __restrict__ gates,
                    __nv_bfloat16* __restrict__ tin)
{
    const int idx = blockIdx.x * 256 + threadIdx.x;   // over B * NH/8
    const int h8 = idx & (NH / 8 - 1);                // 0..63
    const int b  = idx >> 6;
    if (b >= NB) return;

    float g[NTASK][NE];
#pragma unroll
    for (int t = 0; t < NTASK; t++) {
        const float* gp = gates + ((size_t)t * NB + b) * NE;
#pragma unroll
        for (int e = 0; e < NE; e++) g[t][e] = gp[e];
    }

    float o[NTASK][8];
#pragma unroll
    for (int t = 0; t < NTASK; t++)
#pragma unroll
        for (int j = 0; j < 8; j++) o[t][j] = 0.f;

#pragma unroll
    for (int e = 0; e < NE; e++) {
        const __nv_bfloat162* v =
            (const __nv_bfloat162*)(eo + ((size_t)e * NB + b) * NH + h8 * 8);
        float2 f[4];
#pragma unroll
        for (int j = 0; j < 4; j++) f[j] = __bfloat1622float2(v[j]);
#pragma unroll
        for (int t = 0; t < NTASK; t++) {
            const float ge = g[t][e];
#pragma unroll
            for (int j = 0; j < 4; j++) {
                o[t][j * 2 + 0] = fmaf(ge, f[j].x, o[t][j * 2 + 0]);
                o[t][j * 2 + 1] = fmaf(ge, f[j].y, o[t][j * 2 + 1]);
            }
        }
    }
#pragma unroll
    for (int t = 0; t < NTASK; t++) {
        __nv_bfloat162* op = (__nv_bfloat162*)(tin + ((size_t)t * NB + b) * NH + h8 * 8);
#pragma unroll
        for (int j = 0; j < 4; j++)
            op[j] = __floats2bfloat162_rn(o[t][j * 2], o[t][j * 2 + 1]);
    }
}

// ---------------------------------------------------------------------------
// Tower head: pred[t,b] = sigmoid(th[t,b,:] . Wt2[t,:,0] + bt2[t])
// ---------------------------------------------------------------------------
__global__ __launch_bounds__(256)
void tower2_kernel(const float* __restrict__ th, const float* __restrict__ Wt2,
                   const float* __restrict__ bt2, float* __restrict__ out)
{
    const int warp = (blockIdx.x * blockDim.x + threadIdx.x) >> 5;
    const int lane = threadIdx.x & 31;
    if (warp >= NTASK * NB) return;
    const int t = warp / NB;

    const float* row = th + (size_t)warp * NT;
    const float* w   = Wt2 + (size_t)t * NT;
    float acc = 0.f;
#pragma unroll
    for (int d = lane; d < NT; d += 32) acc = fmaf(row[d], w[d], acc);
#pragma unroll
    for (int off = 16; off > 0; off >>= 1)
        acc += __shfl_xor_sync(0xffffffffu, acc, off);
    if (lane == 0) {
        const float zv = acc + bt2[t];
        out[warp] = 1.f / (1.f + expf(-zv));
    }
}

// ---------------------------------------------------------------------------
// Launch
// ---------------------------------------------------------------------------
extern "C" void kernel_launch(void* const* d_in, const int* in_sizes, int n_in,
                              void* d_out, int out_size)
{
    const float* x   = (const float*)d_in[0];
    const float* We1 = (const float*)d_in[1];
    const float* be1 = (const float*)d_in[2];
    const float* We2 = (const float*)d_in[3];
    const float* be2 = (const float*)d_in[4];
    const float* Wg  = (const float*)d_in[5];
    const float* bg  = (const float*)d_in[6];
    const float* Wt1 = (const float*)d_in[7];
    const float* bt1 = (const float*)d_in[8];
    const float* Wt2 = (const float*)d_in[9];
    const float* bt2 = (const float*)d_in[10];
    float* out = (float*)d_out;

    __nv_bfloat16 *xb, *h1b, *eob, *tinb, *We1T, *We2T, *Wt1T;
    float *th, *gates, *WgT;
    cudaGetSymbolAddress((void**)&xb,    g_xb);
    cudaGetSymbolAddress((void**)&h1b,   g_h1b);
    cudaGetSymbolAddress((void**)&eob,   g_eob);
    cudaGetSymbolAddress((void**)&tinb,  g_tinb);
    cudaGetSymbolAddress((void**)&th,    g_th);
    cudaGetSymbolAddress((void**)&gates, g_gates);
    cudaGetSymbolAddress((void**)&WgT,   g_WgT);
    cudaGetSymbolAddress((void**)&We1T,  g_We1T);
    cudaGetSymbolAddress((void**)&We2T,  g_We2T);
    cudaGetSymbolAddress((void**)&Wt1T,  g_Wt1T);

    cudaFuncSetAttribute(gemm_bf16_kernel<__nv_bfloat16>,
                         cudaFuncAttributeMaxDynamicSharedMemorySize, SMEM_BYTES);
    cudaFuncSetAttribute(gemm_bf16_kernel<float>,
                         cudaFuncAttributeMaxDynamicSharedMemorySize, SMEM_BYTES);
    cudaFuncSetAttribute(gates_kernel,
                         cudaFuncAttributeMaxDynamicSharedMemorySize, NTASK * NE * ND * 4);

    // Converts / transposes (one-time prep per call)
    f2b_kernel<<<(NB * ND / 4 + 255) / 256, 256>>>(x, xb, NB * ND / 4);
    transpose_bf16_kernel<<<dim3(NH / 32, ND / 32, NE), 256>>>(We1, We1T, ND, NH);
    transpose_bf16_kernel<<<dim3(NH / 32, NH / 32, NE), 256>>>(We2, We2T, NH, NH);
    transpose_bf16_kernel<<<dim3(NT / 32, NH / 32, NTASK), 256>>>(Wt1, Wt1T, NH, NT);
    wg_transpose_kernel<<<(NTASK * ND * NE + 255) / 256, 256>>>(Wg, WgT);

    // Gates (independent of expert path)
    gates_kernel<<<NB / 32, 256, NTASK * NE * ND * 4>>>(x, WgT, bg, gates);

    // Expert layer 1: h1[e] = relu(x @ We1[e] + be1[e])
    gemm_bf16_kernel<__nv_bfloat16><<<dim3(NH / TN, NB / TM, NE), 256, SMEM_BYTES>>>(
        xb, We1T, be1, h1b, ND, NH,
        0LL, (long long)NH * ND, (long long)NH, (long long)NB * NH);

    // Expert layer 2: eo[e] = relu(h1[e] @ We2[e] + be2[e])
    gemm_bf16_kernel<__nv_bfloat16><<<dim3(NH / TN, NB / TM, NE), 256, SMEM_BYTES>>>(
        h1b, We2T, be2, eob, NH, NH,
        (long long)NB * NH, (long long)NH * NH, (long long)NH, (long long)NB * NH);

    // Gated combine
    combine_kernel<<<(NB * (NH / 8)) / 256, 256>>>(eob, gates, tinb);

    // Tower layer 1: th[t] = relu(tin[t] @ Wt1[t] + bt1[t])  (fp32 out)
    gemm_bf16_kernel<float><<<dim3(NT / TN, NB / TM, NTASK), 256, SMEM_BYTES>>>(
        tinb, Wt1T, bt1, th, NH, NT,
        (long long)NB * NH, (long long)NT * NH, (long long)NT, (long long)NB * NT);

    // Tower head + sigmoid
    tower2_kernel<<<(NTASK * NB * 32) / 256, 256>>>(th, Wt2, bt2, out);
}